// round 9
// baseline (speedup 1.0000x reference)
#include <cuda_runtime.h>
#include <cuda_fp16.h>
#include <math.h>
#include <stdint.h>

// Problem shape (fixed by the dataset)
constexpr int B_  = 8;
constexpr int S_  = 2048;
constexpr int D_  = 1024;
constexpr int DK_ = 128;   // == DV
constexpr int H_  = 4096;  // 4*D
constexpr int R_  = B_ * S_;   // 16384 rows

// ---------------------------------------------------------------------------
// Scratch (device globals -- no dynamic allocation allowed)
// ---------------------------------------------------------------------------
__device__ float  g_xn  [R_ * D_];             // fp32 ln1(x)  (residual source)
__device__ __half g_xnh [R_ * D_];             // fp16 ln1(x)  (GEMM A)
__device__ __half g_qkvh[(size_t)R_ * 384];    // fp16 packed q|k|v
__device__ __half g_hoh [R_ * DK_];            // fp16 attention output
__device__ float  g_y   [R_ * D_];             // fp32 post-attn residual
__device__ __half g_hh  [R_ * D_];             // fp16 ln2(y)
__device__ __half g_midh[(size_t)R_ * H_];     // fp16 MLP hidden
// fp16 weights
__device__ __half g_wqkvh[(size_t)D_ * 384];   // packed Wq|Wk|Wv
__device__ float  g_bqkv [384];
__device__ __half g_woh[DK_ * D_];
__device__ __half g_w1h[(size_t)D_ * H_];
__device__ __half g_w2h[(size_t)H_ * D_];

// ---------------------------------------------------------------------------
// helpers
// ---------------------------------------------------------------------------
__device__ __forceinline__ uint32_t smem_u32(const void* p) {
    uint32_t a;
    asm("{ .reg .u64 t; cvta.to.shared.u64 t, %1; cvt.u32.u64 %0, t; }"
        : "=r"(a) : "l"(p));
    return a;
}
__device__ __forceinline__ void cpasync16(uint32_t dst, const void* src) {
    asm volatile("cp.async.cg.shared.global [%0], [%1], 16;" :: "r"(dst), "l"(src));
}
__device__ __forceinline__ void ldm_x4(uint32_t* r, uint32_t addr) {
    asm volatile("ldmatrix.sync.aligned.m8n8.x4.shared.b16 {%0,%1,%2,%3}, [%4];"
        : "=r"(r[0]), "=r"(r[1]), "=r"(r[2]), "=r"(r[3]) : "r"(addr));
}
__device__ __forceinline__ void ldm_x4_t(uint32_t* r, uint32_t addr) {
    asm volatile("ldmatrix.sync.aligned.m8n8.x4.trans.shared.b16 {%0,%1,%2,%3}, [%4];"
        : "=r"(r[0]), "=r"(r[1]), "=r"(r[2]), "=r"(r[3]) : "r"(addr));
}
__device__ __forceinline__ void mma16(float* c, const uint32_t* a, const uint32_t* b) {
    asm volatile(
        "mma.sync.aligned.m16n8k16.row.col.f32.f16.f16.f32 "
        "{%0,%1,%2,%3},{%4,%5,%6,%7},{%8,%9},{%0,%1,%2,%3};"
        : "+f"(c[0]), "+f"(c[1]), "+f"(c[2]), "+f"(c[3])
        : "r"(a[0]), "r"(a[1]), "r"(a[2]), "r"(a[3]), "r"(b[0]), "r"(b[1]));
}
__device__ __forceinline__ void store2(float* p, float a, float b) {
    *reinterpret_cast<float2*>(p) = make_float2(a, b);
}
__device__ __forceinline__ void store2(__half* p, float a, float b) {
    *reinterpret_cast<__half2*>(p) = __floats2half2_rn(a, b);
}
__device__ __forceinline__ uint32_t packh2(float a, float b) {
    __half2 h = __floats2half2_rn(a, b);
    return *reinterpret_cast<uint32_t*>(&h);
}

// ---------------------------------------------------------------------------
// fp32 -> fp16 elementwise (n % 4 == 0)
// ---------------------------------------------------------------------------
__global__ __launch_bounds__(256)
void f2h_kernel(const float* __restrict__ in, __half* __restrict__ out, int n4)
{
    int i = blockIdx.x * blockDim.x + threadIdx.x;
    if (i < n4) {
        float4 v = reinterpret_cast<const float4*>(in)[i];
        reinterpret_cast<__half2*>(out)[2 * i]     = __floats2half2_rn(v.x, v.y);
        reinterpret_cast<__half2*>(out)[2 * i + 1] = __floats2half2_rn(v.z, v.w);
    }
}

// ---------------------------------------------------------------------------
// Pack Wq|Wk|Wv -> [D, 384] fp16
// ---------------------------------------------------------------------------
__global__ __launch_bounds__(256)
void pack_qkv_w(const float* __restrict__ Wq, const float* __restrict__ Wk,
                const float* __restrict__ Wv, __half* __restrict__ wp)
{
    int i = blockIdx.x * blockDim.x + threadIdx.x;   // over D*DK/2
    if (i >= D_ * DK_ / 2) return;
    int d = (2 * i) / DK_, j2 = ((2 * i) % DK_) / 2;
    float2 a = reinterpret_cast<const float2*>(Wq)[i];
    float2 b = reinterpret_cast<const float2*>(Wk)[i];
    float2 c = reinterpret_cast<const float2*>(Wv)[i];
    __half2* row = reinterpret_cast<__half2*>(wp + (size_t)d * 384);
    row[j2]       = __floats2half2_rn(a.x, a.y);
    row[64 + j2]  = __floats2half2_rn(b.x, b.y);
    row[128 + j2] = __floats2half2_rn(c.x, c.y);
}
__global__ __launch_bounds__(384)
void pack_qkv_b(const float* __restrict__ bq, const float* __restrict__ bk,
                const float* __restrict__ bv, float* __restrict__ bp)
{
    int j = threadIdx.x;
    bp[j] = (j < 128) ? bq[j] : (j < 256) ? bk[j - 128] : bv[j - 256];
}

// ---------------------------------------------------------------------------
// LayerNorm: one block per row, D=1024 -> 256 threads x float4
// ---------------------------------------------------------------------------
template<bool W32, bool W16>
__global__ __launch_bounds__(256)
void ln_kernel(const float* __restrict__ x, const float* __restrict__ g,
               const float* __restrict__ b, float* __restrict__ out32,
               __half* __restrict__ out16)
{
    int row = blockIdx.x;
    int t = threadIdx.x;
    float4 v = reinterpret_cast<const float4*>(x + (size_t)row * D_)[t];
    float s  = v.x + v.y + v.z + v.w;
    float ss = v.x*v.x + v.y*v.y + v.z*v.z + v.w*v.w;
    #pragma unroll
    for (int o = 16; o > 0; o >>= 1) {
        s  += __shfl_xor_sync(0xffffffffu, s,  o);
        ss += __shfl_xor_sync(0xffffffffu, ss, o);
    }
    __shared__ float rs[8], rss[8];
    if ((t & 31) == 0) { rs[t >> 5] = s; rss[t >> 5] = ss; }
    __syncthreads();
    float sum = 0.f, sumsq = 0.f;
    #pragma unroll
    for (int i = 0; i < 8; i++) { sum += rs[i]; sumsq += rss[i]; }
    float mu   = sum * (1.0f / D_);
    float var  = sumsq * (1.0f / D_) - mu * mu;
    float rstd = rsqrtf(var + 1e-5f);
    float4 gg = reinterpret_cast<const float4*>(g)[t];
    float4 bb = reinterpret_cast<const float4*>(b)[t];
    float4 o;
    o.x = (v.x - mu) * rstd * gg.x + bb.x;
    o.y = (v.y - mu) * rstd * gg.y + bb.y;
    o.z = (v.z - mu) * rstd * gg.z + bb.z;
    o.w = (v.w - mu) * rstd * gg.w + bb.w;
    if (W32)
        reinterpret_cast<float4*>(out32 + (size_t)row * D_)[t] = o;
    if (W16) {
        __half2* p = reinterpret_cast<__half2*>(out16 + (size_t)row * D_);
        p[2 * t]     = __floats2half2_rn(o.x, o.y);
        p[2 * t + 1] = __floats2half2_rn(o.z, o.w);
    }
}

// ---------------------------------------------------------------------------
// Flash attention fwd: Q-block 64, K-block 64, 128 threads (4 warps x 16 rows)
// q/k/v packed in qkv[R,384] at column offsets 0/128/256.
// grid (S/64, B); double-buffered K,V; online softmax in exp2 domain.
// ---------------------------------------------------------------------------
constexpr int FA_STRIDE = 136;                       // halves per smem row
constexpr int FA_TILE   = 64 * FA_STRIDE * 2;        // 17408 B
constexpr int FA_SMEM   = 5 * FA_TILE;               // Q + 2*(K,V) = 87040 B
constexpr int FA_NB     = S_ / 64;                   // 32

__global__ __launch_bounds__(128, 2)
void flash_kernel(const __half* __restrict__ qkv, __half* __restrict__ o,
                  float scale2)      // scale * log2(e)
{
    extern __shared__ char smem[];
    const uint32_t smQ  = smem_u32(smem);
    const uint32_t smKV = smQ + FA_TILE;             // [buf][K|V]
    const int tid = threadIdx.x, lane = tid & 31, wid = tid >> 5;
    const int g = lane >> 2, tq = lane & 3;
    const int batch = blockIdx.y, qblk = blockIdx.x;

    const __half* Qg = qkv + ((size_t)batch * S_ + qblk * 64) * 384;
    const __half* Kg = qkv + (size_t)batch * S_ * 384 + 128;
    const __half* Vg = qkv + (size_t)batch * S_ * 384 + 256;

    // tile loader: 128 threads, 64 rows x 256B; source row stride 384 halves
    const int lr = tid >> 1, lc = (tid & 1) * 64;
    const uint32_t ldst = (uint32_t)(lr * FA_STRIDE + lc) * 2;
    auto load_tile = [&](uint32_t smbase, const __half* src) {
        const __half* s = src + (size_t)lr * 384 + lc;
        #pragma unroll
        for (int i = 0; i < 8; i++)
            cpasync16(smbase + ldst + i * 16, s + i * 8);
    };

    load_tile(smQ, Qg);
    load_tile(smKV, Kg);
    load_tile(smKV + FA_TILE, Vg);
    asm volatile("cp.async.commit_group;" ::: "memory");

    float o_acc[16][4];
    #pragma unroll
    for (int i = 0; i < 16; i++)
        #pragma unroll
        for (int r = 0; r < 4; r++) o_acc[i][r] = 0.f;
    float m0 = -INFINITY, m1 = -INFINITY, l0 = 0.f, l1 = 0.f;

    const uint32_t aQ = smQ +
        (uint32_t)(((wid * 16 + (lane & 15)) * FA_STRIDE + (lane >> 4) * 8) * 2);
    const uint32_t fragoff =
        (uint32_t)(((lane & 15) * FA_STRIDE + (lane >> 4) * 8) * 2);

    for (int j = 0; j < FA_NB; j++) {
        const uint32_t smK = smKV + (j & 1) * 2 * FA_TILE;
        const uint32_t smV = smK + FA_TILE;
        __syncthreads();   // everyone done reading the buffer we overwrite next
        if (j + 1 < FA_NB) {
            const uint32_t nK = smKV + ((j + 1) & 1) * 2 * FA_TILE;
            load_tile(nK, Kg + (size_t)(j + 1) * 64 * 384);
            load_tile(nK + FA_TILE, Vg + (size_t)(j + 1) * 64 * 384);
            asm volatile("cp.async.commit_group;" ::: "memory");
            asm volatile("cp.async.wait_group 1;" ::: "memory");
        } else {
            asm volatile("cp.async.wait_group 0;" ::: "memory");
        }
        __syncthreads();

        // ---- S = Q @ K^T  (warp: 16 q-rows x 64 keys) ----
        float sca[8][4];
        #pragma unroll
        for (int i = 0; i < 8; i++)
            #pragma unroll
            for (int r = 0; r < 4; r++) sca[i][r] = 0.f;
        const uint32_t bK = smK + fragoff;
        #pragma unroll
        for (int dc = 0; dc < 8; dc++) {
            uint32_t af[4];
            ldm_x4(af, aQ + dc * 32);
            #pragma unroll
            for (int kb = 0; kb < 4; kb++) {
                uint32_t bf[4];
                ldm_x4(bf, bK + (uint32_t)((kb * 16 * FA_STRIDE + dc * 16) * 2));
                uint32_t b0[2] = { bf[0], bf[2] };
                uint32_t b1[2] = { bf[1], bf[3] };
                mma16(sca[2 * kb],     af, b0);
                mma16(sca[2 * kb + 1], af, b1);
            }
        }

        // ---- online softmax (base-2 domain) ----
        float mr0 = -INFINITY, mr1 = -INFINITY;
        #pragma unroll
        for (int jb = 0; jb < 8; jb++) {
            mr0 = fmaxf(mr0, fmaxf(sca[jb][0], sca[jb][1]));
            mr1 = fmaxf(mr1, fmaxf(sca[jb][2], sca[jb][3]));
        }
        mr0 = fmaxf(mr0, __shfl_xor_sync(0xffffffffu, mr0, 1));
        mr0 = fmaxf(mr0, __shfl_xor_sync(0xffffffffu, mr0, 2));
        mr1 = fmaxf(mr1, __shfl_xor_sync(0xffffffffu, mr1, 1));
        mr1 = fmaxf(mr1, __shfl_xor_sync(0xffffffffu, mr1, 2));
        float mn0 = fmaxf(m0, mr0 * scale2);
        float mn1 = fmaxf(m1, mr1 * scale2);
        float c0 = exp2f(m0 - mn0);
        float c1 = exp2f(m1 - mn1);
        m0 = mn0; m1 = mn1;
        #pragma unroll
        for (int jb = 0; jb < 16; jb++) {
            o_acc[jb][0] *= c0; o_acc[jb][1] *= c0;
            o_acc[jb][2] *= c1; o_acc[jb][3] *= c1;
        }
        float ps0 = 0.f, ps1 = 0.f;
        uint32_t ph[8][2];
        #pragma unroll
        for (int jb = 0; jb < 8; jb++) {
            float p0 = exp2f(sca[jb][0] * scale2 - mn0);
            float p1 = exp2f(sca[jb][1] * scale2 - mn0);
            float p2 = exp2f(sca[jb][2] * scale2 - mn1);
            float p3 = exp2f(sca[jb][3] * scale2 - mn1);
            ps0 += p0 + p1; ps1 += p2 + p3;
            ph[jb][0] = packh2(p0, p1);
            ph[jb][1] = packh2(p2, p3);
        }
        ps0 += __shfl_xor_sync(0xffffffffu, ps0, 1);
        ps0 += __shfl_xor_sync(0xffffffffu, ps0, 2);
        ps1 += __shfl_xor_sync(0xffffffffu, ps1, 1);
        ps1 += __shfl_xor_sync(0xffffffffu, ps1, 2);
        l0 = l0 * c0 + ps0;
        l1 = l1 * c1 + ps1;

        // ---- O += P @ V ----
        const uint32_t bV = smV + fragoff;
        #pragma unroll
        for (int j2 = 0; j2 < 4; j2++) {
            uint32_t paf[4] = { ph[2 * j2][0], ph[2 * j2][1],
                                ph[2 * j2 + 1][0], ph[2 * j2 + 1][1] };
            #pragma unroll
            for (int db = 0; db < 8; db++) {
                uint32_t bf[4];
                ldm_x4_t(bf, bV + (uint32_t)((j2 * 16 * FA_STRIDE + db * 16) * 2));
                mma16(o_acc[2 * db],     paf, bf);
                mma16(o_acc[2 * db + 1], paf, bf + 2);
            }
        }
    }

    // ---- epilogue ----
    const float i0 = 1.f / l0, i1 = 1.f / l1;
    const int row0 = qblk * 64 + wid * 16 + g;
    __half* O0 = o + ((size_t)batch * S_ + row0) * DK_;
    #pragma unroll
    for (int jb = 0; jb < 16; jb++) {
        const int d = jb * 8 + 2 * tq;
        store2(O0 + d,            o_acc[jb][0] * i0, o_acc[jb][1] * i0);
        store2(O0 + 8 * DK_ + d,  o_acc[jb][2] * i1, o_acc[jb][3] * i1);
    }
}

// ---------------------------------------------------------------------------
// fp16 mma.sync GEMM:  C[M,N] = A[M,K] @ B[K,N]  (NN)
// CTA 128x128x32, 256 threads = 8 warps (2m x 4n), warp tile 64x32.
// 4-stage cp.async pipeline; ldmatrix fragment loads; padded smem rows.
// EPI: 1 +bias | 2 +bias+gelu | 3 +bias+residual(fp32)
// ---------------------------------------------------------------------------
constexpr int A_STRIDE = 40;
constexpr int B_STRIDE = 136;
constexpr int SA_BYTES = 128 * A_STRIDE * 2;            // 10240
constexpr int SB_BYTES = 32 * B_STRIDE * 2;             // 8704
constexpr int STAGE_BYTES = SA_BYTES + SB_BYTES;        // 18944
constexpr int N_STAGE = 4;
constexpr int SM_TOT = N_STAGE * STAGE_BYTES;           // 75776

template<int EPI, typename TO>
__global__ __launch_bounds__(256)
void gemm_h(const __half* __restrict__ A, const __half* __restrict__ Bm,
            const float* __restrict__ bias, const float* __restrict__ res,
            TO* __restrict__ C, int M, int N, int K)
{
    extern __shared__ char smem[];
    const uint32_t sm0 = smem_u32(smem);
    const int tid = threadIdx.x, lane = tid & 31, wid = tid >> 5;
    const int wm = wid >> 2, wn = wid & 3;
    const int g = lane >> 2, tq = lane & 3;
    const int mb = blockIdx.y * 128, nb = blockIdx.x * 128;

    const __half* Ab = A + (size_t)mb * K;
    const __half* Bb = Bm + nb;
    TO*           Cb = C;
    const float*  Rb = (EPI == 3) ? res : nullptr;

    const int ar = tid >> 1, ac = (tid & 1) * 2;
    const int bkr = tid >> 3, bcc = (tid & 7) * 2;
    const uint32_t a_dst = sm0 + (uint32_t)(ar * A_STRIDE + ac * 8) * 2;
    const uint32_t b_dst = sm0 + SA_BYTES + (uint32_t)(bkr * B_STRIDE + bcc * 8) * 2;
    const __half* a_src = Ab + (size_t)ar * K + ac * 8;
    const __half* b_src = Bb + (size_t)bkr * N + bcc * 8;

    auto load = [&](int c, int s) {
        uint32_t ad = a_dst + s * STAGE_BYTES;
        uint32_t bd = b_dst + s * STAGE_BYTES;
        const __half* as = a_src + c * 32;
        const __half* bs = b_src + (size_t)c * 32 * N;
        cpasync16(ad,      as);
        cpasync16(ad + 16, as + 8);
        cpasync16(bd,      bs);
        cpasync16(bd + 16, bs + 8);
        asm volatile("cp.async.commit_group;" ::: "memory");
    };

    const uint32_t a_frag = sm0 +
        (uint32_t)(((wm * 64 + (lane & 15)) * A_STRIDE + (lane >> 4) * 8) * 2);
    const uint32_t b_frag = sm0 + SA_BYTES +
        (uint32_t)(((lane & 15) * B_STRIDE + wn * 32 + (lane >> 4) * 8) * 2);

    float acc[4][4][4];
    #pragma unroll
    for (int i = 0; i < 4; i++)
        #pragma unroll
        for (int j = 0; j < 4; j++)
            #pragma unroll
            for (int r = 0; r < 4; r++) acc[i][j][r] = 0.f;

    const int NC = K / 32;
    #pragma unroll
    for (int s = 0; s < N_STAGE - 1; s++)
        if (s < NC) load(s, s);

    for (int c = 0; c < NC; c++) {
        int ahead = NC - 1 - c;
        if (ahead >= 2)      asm volatile("cp.async.wait_group 2;" ::: "memory");
        else if (ahead == 1) asm volatile("cp.async.wait_group 1;" ::: "memory");
        else                 asm volatile("cp.async.wait_group 0;" ::: "memory");
        __syncthreads();
        if (c + N_STAGE - 1 < NC) load(c + N_STAGE - 1, (c + N_STAGE - 1) & 3);

        const uint32_t au = a_frag + (c & 3) * STAGE_BYTES;
        const uint32_t bu = b_frag + (c & 3) * STAGE_BYTES;
        #pragma unroll
        for (int ks = 0; ks < 2; ks++) {
            uint32_t af[4][4], bf[2][4];
            #pragma unroll
            for (int i = 0; i < 4; i++)
                ldm_x4(af[i], au + i * (16 * A_STRIDE * 2) + ks * 32);
            ldm_x4_t(bf[0], bu + ks * (16 * B_STRIDE * 2));
            ldm_x4_t(bf[1], bu + ks * (16 * B_STRIDE * 2) + 32);
            #pragma unroll
            for (int i = 0; i < 4; i++)
                #pragma unroll
                for (int j = 0; j < 4; j++)
                    mma16(acc[i][j], af[i], &bf[j >> 1][(j & 1) * 2]);
        }
    }

    #pragma unroll
    for (int i = 0; i < 4; i++) {
        const int r0 = mb + wm * 64 + i * 16 + g;
        #pragma unroll
        for (int j = 0; j < 4; j++) {
            const int col = nb + wn * 32 + j * 8 + 2 * tq;
            float v0 = acc[i][j][0], v1 = acc[i][j][1];
            float v2 = acc[i][j][2], v3 = acc[i][j][3];
            {
                float2 bb = *reinterpret_cast<const float2*>(bias + col);
                v0 += bb.x; v1 += bb.y; v2 += bb.x; v3 += bb.y;
            }
            if (EPI == 2) {
                v0 = 0.5f * v0 * (1.0f + erff(v0 * 0.70710678118654752f));
                v1 = 0.5f * v1 * (1.0f + erff(v1 * 0.70710678118654752f));
                v2 = 0.5f * v2 * (1.0f + erff(v2 * 0.70710678118654752f));
                v3 = 0.5f * v3 * (1.0f + erff(v3 * 0.70710678118654752f));
            }
            if (EPI == 3) {
                float2 r1 = *reinterpret_cast<const float2*>(Rb + (size_t)r0 * N + col);
                float2 r2 = *reinterpret_cast<const float2*>(Rb + (size_t)(r0 + 8) * N + col);
                v0 += r1.x; v1 += r1.y; v2 += r2.x; v3 += r2.y;
            }
            store2(Cb + (size_t)r0 * N + col,       v0, v1);
            store2(Cb + (size_t)(r0 + 8) * N + col, v2, v3);
        }
    }
}

// ---------------------------------------------------------------------------
// Launch graph
// ---------------------------------------------------------------------------
extern "C" void kernel_launch(void* const* d_in, const int* in_sizes, int n_in,
                              void* d_out, int out_size)
{
    (void)in_sizes; (void)n_in; (void)out_size;
    const float* x    = (const float*)d_in[0];
    const float* ln1g = (const float*)d_in[1];
    const float* ln1b = (const float*)d_in[2];
    const float* Wq   = (const float*)d_in[3];
    const float* bq   = (const float*)d_in[4];
    const float* Wk   = (const float*)d_in[5];
    const float* bk   = (const float*)d_in[6];
    const float* Wv   = (const float*)d_in[7];
    const float* bv   = (const float*)d_in[8];
    const float* Wo   = (const float*)d_in[9];
    const float* bo   = (const float*)d_in[10];
    const float* ln2g = (const float*)d_in[11];
    const float* ln2b = (const float*)d_in[12];
    const float* W1   = (const float*)d_in[13];
    const float* b1   = (const float*)d_in[14];
    const float* W2   = (const float*)d_in[15];
    const float* b2   = (const float*)d_in[16];
    float* out = (float*)d_out;

    float *xn, *y, *bqkv;
    __half *xnh, *qkvh, *hoh, *hh, *midh;
    __half *wqkvh, *woh, *w1h, *w2h;
    cudaGetSymbolAddress((void**)&xn,    g_xn);
    cudaGetSymbolAddress((void**)&xnh,   g_xnh);
    cudaGetSymbolAddress((void**)&qkvh,  g_qkvh);
    cudaGetSymbolAddress((void**)&hoh,   g_hoh);
    cudaGetSymbolAddress((void**)&y,     g_y);
    cudaGetSymbolAddress((void**)&hh,    g_hh);
    cudaGetSymbolAddress((void**)&midh,  g_midh);
    cudaGetSymbolAddress((void**)&wqkvh, g_wqkvh);
    cudaGetSymbolAddress((void**)&bqkv,  g_bqkv);
    cudaGetSymbolAddress((void**)&woh,   g_woh);
    cudaGetSymbolAddress((void**)&w1h,   g_w1h);
    cudaGetSymbolAddress((void**)&w2h,   g_w2h);

    cudaFuncSetAttribute(gemm_h<1, __half>, cudaFuncAttributeMaxDynamicSharedMemorySize, SM_TOT);
    cudaFuncSetAttribute(gemm_h<2, __half>, cudaFuncAttributeMaxDynamicSharedMemorySize, SM_TOT);
    cudaFuncSetAttribute(gemm_h<3, float>,  cudaFuncAttributeMaxDynamicSharedMemorySize, SM_TOT);
    cudaFuncSetAttribute(flash_kernel, cudaFuncAttributeMaxDynamicSharedMemorySize, FA_SMEM);

    const float scale2 = 0.08838834764831845f * 1.4426950408889634f; // /sqrt(128)*log2e

    // 0. pack / convert weights to fp16
    pack_qkv_w<<<(D_ * DK_ / 2 + 255) / 256, 256>>>(Wq, Wk, Wv, wqkvh);
    pack_qkv_b<<<1, 384>>>(bq, bk, bv, bqkv);
    f2h_kernel<<<(DK_ * D_ / 4 + 255) / 256, 256>>>(Wo, woh, DK_ * D_ / 4);
    f2h_kernel<<<(D_ * H_ / 4 + 255) / 256, 256>>>(W1, w1h, D_ * H_ / 4);
    f2h_kernel<<<(H_ * D_ / 4 + 255) / 256, 256>>>(W2, w2h, H_ * D_ / 4);

    // 1. xn = LN1(x)  (fp32 + fp16)
    ln_kernel<true, true><<<R_, 256>>>(x, ln1g, ln1b, xn, xnh);

    // 2. qkv = xnh @ Wqkv + bqkv  -> fp16 [R,384]
    gemm_h<1, __half><<<dim3(3, 128, 1), 256, SM_TOT>>>(xnh, wqkvh, bqkv, nullptr, qkvh, R_, 384, D_);

    // 3. flash attention -> fp16 ho
    flash_kernel<<<dim3(S_ / 64, B_), 128, FA_SMEM>>>(qkvh, hoh, scale2);

    // 4. y = xn + ho @ Wo + bo  -> fp32
    gemm_h<3, float><<<dim3(8, 128, 1), 256, SM_TOT>>>(hoh, woh, bo, xn, y, R_, D_, DK_);

    // 5. h = LN2(y) -> fp16
    ln_kernel<false, true><<<R_, 256>>>(y, ln2g, ln2b, nullptr, hh);

    // 6. mid = gelu(h @ W1 + b1)  -> fp16
    gemm_h<2, __half><<<dim3(32, 128, 1), 256, SM_TOT>>>(hh, w1h, b1, nullptr, midh, R_, H_, D_);

    // 7. out = y + mid @ W2 + b2  -> fp32
    gemm_h<3, float><<<dim3(8, 128, 1), 256, SM_TOT>>>(midh, w2h, b2, y, out, R_, D_, H_);
}

// round 13
// speedup vs baseline: 1.0809x; 1.0809x over previous
#include <cuda_runtime.h>
#include <cuda_fp16.h>
#include <math.h>
#include <stdint.h>

// Problem shape (fixed by the dataset)
constexpr int B_  = 8;
constexpr int S_  = 2048;
constexpr int D_  = 1024;
constexpr int DK_ = 128;   // == DV
constexpr int H_  = 4096;  // 4*D
constexpr int R_  = B_ * S_;   // 16384 rows

// ---------------------------------------------------------------------------
// Scratch (device globals -- no dynamic allocation allowed)
// ---------------------------------------------------------------------------
__device__ float  g_xn  [R_ * D_];             // fp32 ln1(x)  (residual source)
__device__ __half g_xnh [R_ * D_];             // fp16 ln1(x)  (GEMM A)
__device__ __half g_qkvh[(size_t)R_ * 384];    // fp16 packed q|k|v
__device__ __half g_hoh [R_ * DK_];            // fp16 attention output
__device__ float  g_y   [R_ * D_];             // fp32 post-attn residual
__device__ __half g_hh  [R_ * D_];             // fp16 ln2(y)
__device__ __half g_midh[(size_t)R_ * H_];     // fp16 MLP hidden
// fp16 weights
__device__ __half g_wqkvh[(size_t)D_ * 384];   // packed Wq|Wk|Wv
__device__ float  g_bqkv [384];
__device__ __half g_woh[DK_ * D_];
__device__ __half g_w1h[(size_t)D_ * H_];
__device__ __half g_w2h[(size_t)H_ * D_];

// ---------------------------------------------------------------------------
// helpers
// ---------------------------------------------------------------------------
__device__ __forceinline__ uint32_t smem_u32(const void* p) {
    uint32_t a;
    asm("{ .reg .u64 t; cvta.to.shared.u64 t, %1; cvt.u32.u64 %0, t; }"
        : "=r"(a) : "l"(p));
    return a;
}
__device__ __forceinline__ void cpasync16(uint32_t dst, const void* src) {
    asm volatile("cp.async.cg.shared.global [%0], [%1], 16;" :: "r"(dst), "l"(src));
}
__device__ __forceinline__ void ldm_x4(uint32_t* r, uint32_t addr) {
    asm volatile("ldmatrix.sync.aligned.m8n8.x4.shared.b16 {%0,%1,%2,%3}, [%4];"
        : "=r"(r[0]), "=r"(r[1]), "=r"(r[2]), "=r"(r[3]) : "r"(addr));
}
__device__ __forceinline__ void ldm_x4_t(uint32_t* r, uint32_t addr) {
    asm volatile("ldmatrix.sync.aligned.m8n8.x4.trans.shared.b16 {%0,%1,%2,%3}, [%4];"
        : "=r"(r[0]), "=r"(r[1]), "=r"(r[2]), "=r"(r[3]) : "r"(addr));
}
__device__ __forceinline__ void mma16(float* c, const uint32_t* a, const uint32_t* b) {
    asm volatile(
        "mma.sync.aligned.m16n8k16.row.col.f32.f16.f16.f32 "
        "{%0,%1,%2,%3},{%4,%5,%6,%7},{%8,%9},{%0,%1,%2,%3};"
        : "+f"(c[0]), "+f"(c[1]), "+f"(c[2]), "+f"(c[3])
        : "r"(a[0]), "r"(a[1]), "r"(a[2]), "r"(a[3]), "r"(b[0]), "r"(b[1]));
}
__device__ __forceinline__ void store2(float* p, float a, float b) {
    *reinterpret_cast<float2*>(p) = make_float2(a, b);
}
__device__ __forceinline__ void store2(__half* p, float a, float b) {
    *reinterpret_cast<__half2*>(p) = __floats2half2_rn(a, b);
}
__device__ __forceinline__ uint32_t packh2(float a, float b) {
    __half2 h = __floats2half2_rn(a, b);
    return *reinterpret_cast<uint32_t*>(&h);
}

// ---------------------------------------------------------------------------
// Single prep kernel: pack Wqkv -> [D,384] fp16, bqkv, convert Wo/W1/W2
// ---------------------------------------------------------------------------
constexpr int PK_QKV = D_ * DK_ / 2;              //  65536  (float2 granularity)
constexpr int PK_WO  = DK_ * D_ / 4;              //  32768  (float4)
constexpr int PK_W1  = D_ * H_ / 4;               // 1048576 (float4)
constexpr int PK_W2  = H_ * D_ / 4;               // 1048576 (float4)
constexpr int PK_TOT = PK_QKV + PK_WO + PK_W1 + PK_W2 + 384;

__global__ __launch_bounds__(256)
void prep_kernel(const float* __restrict__ Wq, const float* __restrict__ Wk,
                 const float* __restrict__ Wv,
                 const float* __restrict__ bq, const float* __restrict__ bk,
                 const float* __restrict__ bv,
                 const float* __restrict__ Wo, const float* __restrict__ W1,
                 const float* __restrict__ W2,
                 __half* __restrict__ wqkv, float* __restrict__ bqkv,
                 __half* __restrict__ wo, __half* __restrict__ w1,
                 __half* __restrict__ w2)
{
    int id = blockIdx.x * blockDim.x + threadIdx.x;
    if (id < PK_QKV) {
        int i = id;
        int d = (2 * i) / DK_, j2 = ((2 * i) % DK_) / 2;
        float2 a = reinterpret_cast<const float2*>(Wq)[i];
        float2 b = reinterpret_cast<const float2*>(Wk)[i];
        float2 c = reinterpret_cast<const float2*>(Wv)[i];
        __half2* row = reinterpret_cast<__half2*>(wqkv + (size_t)d * 384);
        row[j2]       = __floats2half2_rn(a.x, a.y);
        row[64 + j2]  = __floats2half2_rn(b.x, b.y);
        row[128 + j2] = __floats2half2_rn(c.x, c.y);
        return;
    }
    id -= PK_QKV;
    if (id < PK_WO) {
        float4 v = reinterpret_cast<const float4*>(Wo)[id];
        reinterpret_cast<__half2*>(wo)[2 * id]     = __floats2half2_rn(v.x, v.y);
        reinterpret_cast<__half2*>(wo)[2 * id + 1] = __floats2half2_rn(v.z, v.w);
        return;
    }
    id -= PK_WO;
    if (id < PK_W1) {
        float4 v = reinterpret_cast<const float4*>(W1)[id];
        reinterpret_cast<__half2*>(w1)[2 * id]     = __floats2half2_rn(v.x, v.y);
        reinterpret_cast<__half2*>(w1)[2 * id + 1] = __floats2half2_rn(v.z, v.w);
        return;
    }
    id -= PK_W1;
    if (id < PK_W2) {
        float4 v = reinterpret_cast<const float4*>(W2)[id];
        reinterpret_cast<__half2*>(w2)[2 * id]     = __floats2half2_rn(v.x, v.y);
        reinterpret_cast<__half2*>(w2)[2 * id + 1] = __floats2half2_rn(v.z, v.w);
        return;
    }
    id -= PK_W2;
    if (id < 384)
        bqkv[id] = (id < 128) ? bq[id] : (id < 256) ? bk[id - 128] : bv[id - 256];
}

// ---------------------------------------------------------------------------
// LayerNorm: one block per row, D=1024 -> 256 threads x float4
// ---------------------------------------------------------------------------
template<bool W32, bool W16>
__global__ __launch_bounds__(256)
void ln_kernel(const float* __restrict__ x, const float* __restrict__ g,
               const float* __restrict__ b, float* __restrict__ out32,
               __half* __restrict__ out16)
{
    int row = blockIdx.x;
    int t = threadIdx.x;
    float4 v = reinterpret_cast<const float4*>(x + (size_t)row * D_)[t];
    float s  = v.x + v.y + v.z + v.w;
    float ss = v.x*v.x + v.y*v.y + v.z*v.z + v.w*v.w;
    #pragma unroll
    for (int o = 16; o > 0; o >>= 1) {
        s  += __shfl_xor_sync(0xffffffffu, s,  o);
        ss += __shfl_xor_sync(0xffffffffu, ss, o);
    }
    __shared__ float rs[8], rss[8];
    if ((t & 31) == 0) { rs[t >> 5] = s; rss[t >> 5] = ss; }
    __syncthreads();
    float sum = 0.f, sumsq = 0.f;
    #pragma unroll
    for (int i = 0; i < 8; i++) { sum += rs[i]; sumsq += rss[i]; }
    float mu   = sum * (1.0f / D_);
    float var  = sumsq * (1.0f / D_) - mu * mu;
    float rstd = rsqrtf(var + 1e-5f);
    float4 gg = reinterpret_cast<const float4*>(g)[t];
    float4 bb = reinterpret_cast<const float4*>(b)[t];
    float4 o;
    o.x = (v.x - mu) * rstd * gg.x + bb.x;
    o.y = (v.y - mu) * rstd * gg.y + bb.y;
    o.z = (v.z - mu) * rstd * gg.z + bb.z;
    o.w = (v.w - mu) * rstd * gg.w + bb.w;
    if (W32)
        reinterpret_cast<float4*>(out32 + (size_t)row * D_)[t] = o;
    if (W16) {
        __half2* p = reinterpret_cast<__half2*>(out16 + (size_t)row * D_);
        p[2 * t]     = __floats2half2_rn(o.x, o.y);
        p[2 * t + 1] = __floats2half2_rn(o.z, o.w);
    }
}

// ---------------------------------------------------------------------------
// Flash attention fwd: Q-block 128, K-block 128, 256 threads (8 warps x 16 rows)
// q/k/v packed in qkv[R,384] at column offsets 0/128/256 (row stride 384).
// grid (S/128, B); double-buffered K,V; online softmax in exp2 domain.
// ---------------------------------------------------------------------------
constexpr int FA_STRIDE = 136;                    // halves per smem row (272 B)
constexpr int FA_TILE   = 128 * FA_STRIDE * 2;    // 34816 B
constexpr int FA_SMEM   = 5 * FA_TILE;            // Q + 2*(K,V) = 174080 B
constexpr int FA_NB     = S_ / 128;               // 16

__global__ __launch_bounds__(256, 1)
void flash_kernel(const __half* __restrict__ qkv, __half* __restrict__ o,
                  float scale2)      // scale * log2(e)
{
    extern __shared__ char smem[];
    const uint32_t smQ  = smem_u32(smem);
    const uint32_t smKV = smQ + FA_TILE;          // [buf][K|V]
    const int tid = threadIdx.x, lane = tid & 31, wid = tid >> 5;
    const int g = lane >> 2, tq = lane & 3;
    const int batch = blockIdx.y, qblk = blockIdx.x;

    const __half* Qg = qkv + ((size_t)batch * S_ + qblk * 128) * 384;
    const __half* Kg = qkv + (size_t)batch * S_ * 384 + 128;
    const __half* Vg = qkv + (size_t)batch * S_ * 384 + 256;

    // tile loader: 256 threads x 128B; source row stride 384 halves
    const int lr = tid >> 1, lc = (tid & 1) * 64;
    const uint32_t ldst = (uint32_t)(lr * FA_STRIDE + lc) * 2;
    auto load_tile = [&](uint32_t smbase, const __half* src) {
        const __half* s = src + (size_t)lr * 384 + lc;
        #pragma unroll
        for (int i = 0; i < 8; i++)
            cpasync16(smbase + ldst + i * 16, s + i * 8);
    };

    load_tile(smQ, Qg);
    load_tile(smKV, Kg);
    load_tile(smKV + FA_TILE, Vg);
    asm volatile("cp.async.commit_group;" ::: "memory");

    float o_acc[16][4];
    #pragma unroll
    for (int i = 0; i < 16; i++)
        #pragma unroll
        for (int r = 0; r < 4; r++) o_acc[i][r] = 0.f;
    float m0 = -INFINITY, m1 = -INFINITY, l0 = 0.f, l1 = 0.f;

    const uint32_t aQ = smQ +
        (uint32_t)(((wid * 16 + (lane & 15)) * FA_STRIDE + (lane >> 4) * 8) * 2);
    const uint32_t fragoff =
        (uint32_t)(((lane & 15) * FA_STRIDE + (lane >> 4) * 8) * 2);

    for (int j = 0; j < FA_NB; j++) {
        const uint32_t smK = smKV + (j & 1) * 2 * FA_TILE;
        const uint32_t smV = smK + FA_TILE;
        __syncthreads();   // everyone done reading the buffer we overwrite next
        if (j + 1 < FA_NB) {
            const uint32_t nK = smKV + ((j + 1) & 1) * 2 * FA_TILE;
            load_tile(nK, Kg + (size_t)(j + 1) * 128 * 384);
            load_tile(nK + FA_TILE, Vg + (size_t)(j + 1) * 128 * 384);
            asm volatile("cp.async.commit_group;" ::: "memory");
            asm volatile("cp.async.wait_group 1;" ::: "memory");
        } else {
            asm volatile("cp.async.wait_group 0;" ::: "memory");
        }
        __syncthreads();

        // ---- S = Q @ K^T  (warp: 16 q-rows x 128 keys) ----
        float sca[16][4];
        #pragma unroll
        for (int i = 0; i < 16; i++)
            #pragma unroll
            for (int r = 0; r < 4; r++) sca[i][r] = 0.f;
        const uint32_t bK = smK + fragoff;
        #pragma unroll
        for (int dc = 0; dc < 8; dc++) {
            uint32_t af[4];
            ldm_x4(af, aQ + dc * 32);
            #pragma unroll
            for (int kb = 0; kb < 8; kb++) {
                uint32_t bf[4];
                ldm_x4(bf, bK + (uint32_t)((kb * 16 * FA_STRIDE + dc * 16) * 2));
                uint32_t b0[2] = { bf[0], bf[2] };
                uint32_t b1[2] = { bf[1], bf[3] };
                mma16(sca[2 * kb],     af, b0);
                mma16(sca[2 * kb + 1], af, b1);
            }
        }

        // ---- online softmax (base-2 domain) ----
        float mr0 = -INFINITY, mr1 = -INFINITY;
        #pragma unroll
        for (int jb = 0; jb < 16; jb++) {
            mr0 = fmaxf(mr0, fmaxf(sca[jb][0], sca[jb][1]));
            mr1 = fmaxf(mr1, fmaxf(sca[jb][2], sca[jb][3]));
        }
        mr0 = fmaxf(mr0, __shfl_xor_sync(0xffffffffu, mr0, 1));
        mr0 = fmaxf(mr0, __shfl_xor_sync(0xffffffffu, mr0, 2));
        mr1 = fmaxf(mr1, __shfl_xor_sync(0xffffffffu, mr1, 1));
        mr1 = fmaxf(mr1, __shfl_xor_sync(0xffffffffu, mr1, 2));
        float mn0 = fmaxf(m0, mr0 * scale2);
        float mn1 = fmaxf(m1, mr1 * scale2);
        float c0 = exp2f(m0 - mn0);
        float c1 = exp2f(m1 - mn1);
        m0 = mn0; m1 = mn1;
        #pragma unroll
        for (int jb = 0; jb < 16; jb++) {
            o_acc[jb][0] *= c0; o_acc[jb][1] *= c0;
            o_acc[jb][2] *= c1; o_acc[jb][3] *= c1;
        }
        float ps0 = 0.f, ps1 = 0.f;
        uint32_t ph[16][2];
        #pragma unroll
        for (int jb = 0; jb < 16; jb++) {
            float p0 = exp2f(sca[jb][0] * scale2 - mn0);
            float p1 = exp2f(sca[jb][1] * scale2 - mn0);
            float p2 = exp2f(sca[jb][2] * scale2 - mn1);
            float p3 = exp2f(sca[jb][3] * scale2 - mn1);
            ps0 += p0 + p1; ps1 += p2 + p3;
            ph[jb][0] = packh2(p0, p1);
            ph[jb][1] = packh2(p2, p3);
        }
        ps0 += __shfl_xor_sync(0xffffffffu, ps0, 1);
        ps0 += __shfl_xor_sync(0xffffffffu, ps0, 2);
        ps1 += __shfl_xor_sync(0xffffffffu, ps1, 1);
        ps1 += __shfl_xor_sync(0xffffffffu, ps1, 2);
        l0 = l0 * c0 + ps0;
        l1 = l1 * c1 + ps1;

        // ---- O += P @ V ----
        const uint32_t bV = smV + fragoff;
        #pragma unroll
        for (int j2 = 0; j2 < 8; j2++) {
            uint32_t paf[4] = { ph[2 * j2][0], ph[2 * j2][1],
                                ph[2 * j2 + 1][0], ph[2 * j2 + 1][1] };
            #pragma unroll
            for (int db = 0; db < 8; db++) {
                uint32_t bf[4];
                ldm_x4_t(bf, bV + (uint32_t)((j2 * 16 * FA_STRIDE + db * 16) * 2));
                mma16(o_acc[2 * db],     paf, bf);
                mma16(o_acc[2 * db + 1], paf, bf + 2);
            }
        }
    }

    // ---- epilogue ----
    const float i0 = 1.f / l0, i1 = 1.f / l1;
    const int row0 = qblk * 128 + wid * 16 + g;
    __half* O0 = o + ((size_t)batch * S_ + row0) * DK_;
    #pragma unroll
    for (int jb = 0; jb < 16; jb++) {
        const int d = jb * 8 + 2 * tq;
        store2(O0 + d,            o_acc[jb][0] * i0, o_acc[jb][1] * i0);
        store2(O0 + 8 * DK_ + d,  o_acc[jb][2] * i1, o_acc[jb][3] * i1);
    }
}

// ---------------------------------------------------------------------------
// fp16 mma.sync GEMM:  C[M,N] = A[M,K] @ B[K,N]  (NN)
// CTA 128x128x32, 256 threads = 8 warps (2m x 4n), warp tile 64x32.
// 4-stage cp.async pipeline; ldmatrix fragment loads; padded smem rows.
// __launch_bounds__(256, 2): cap 128 regs/thread -> 2 CTAs/SM (16 warps).
// EPI: 1 +bias | 2 +bias+gelu | 3 +bias+residual(fp32)
// ---------------------------------------------------------------------------
constexpr int A_STRIDE = 40;
constexpr int B_STRIDE = 136;
constexpr int SA_BYTES = 128 * A_STRIDE * 2;            // 10240
constexpr int SB_BYTES = 32 * B_STRIDE * 2;             // 8704
constexpr int STAGE_BYTES = SA_BYTES + SB_BYTES;        // 18944
constexpr int N_STAGE = 4;
constexpr int SM_TOT = N_STAGE * STAGE_BYTES;           // 75776

template<int EPI, typename TO>
__global__ __launch_bounds__(256, 2)
void gemm_h(const __half* __restrict__ A, const __half* __restrict__ Bm,
            const float* __restrict__ bias, const float* __restrict__ res,
            TO* __restrict__ C, int M, int N, int K)
{
    extern __shared__ char smem[];
    const uint32_t sm0 = smem_u32(smem);
    const int tid = threadIdx.x, lane = tid & 31, wid = tid >> 5;
    const int wm = wid >> 2, wn = wid & 3;
    const int g = lane >> 2, tq = lane & 3;
    const int mb = blockIdx.y * 128, nb = blockIdx.x * 128;

    const __half* Ab = A + (size_t)mb * K;
    const __half* Bb = Bm + nb;
    TO*           Cb = C;
    const float*  Rb = (EPI == 3) ? res : nullptr;

    const int ar = tid >> 1, ac = (tid & 1) * 2;
    const int bkr = tid >> 3, bcc = (tid & 7) * 2;
    const uint32_t a_dst = sm0 + (uint32_t)(ar * A_STRIDE + ac * 8) * 2;
    const uint32_t b_dst = sm0 + SA_BYTES + (uint32_t)(bkr * B_STRIDE + bcc * 8) * 2;
    const __half* a_src = Ab + (size_t)ar * K + ac * 8;
    const __half* b_src = Bb + (size_t)bkr * N + bcc * 8;

    auto load = [&](int c, int s) {
        uint32_t ad = a_dst + s * STAGE_BYTES;
        uint32_t bd = b_dst + s * STAGE_BYTES;
        const __half* as = a_src + c * 32;
        const __half* bs = b_src + (size_t)c * 32 * N;
        cpasync16(ad,      as);
        cpasync16(ad + 16, as + 8);
        cpasync16(bd,      bs);
        cpasync16(bd + 16, bs + 8);
        asm volatile("cp.async.commit_group;" ::: "memory");
    };

    const uint32_t a_frag = sm0 +
        (uint32_t)(((wm * 64 + (lane & 15)) * A_STRIDE + (lane >> 4) * 8) * 2);
    const uint32_t b_frag = sm0 + SA_BYTES +
        (uint32_t)(((lane & 15) * B_STRIDE + wn * 32 + (lane >> 4) * 8) * 2);

    float acc[4][4][4];
    #pragma unroll
    for (int i = 0; i < 4; i++)
        #pragma unroll
        for (int j = 0; j < 4; j++)
            #pragma unroll
            for (int r = 0; r < 4; r++) acc[i][j][r] = 0.f;

    const int NC = K / 32;
    #pragma unroll
    for (int s = 0; s < N_STAGE - 1; s++)
        if (s < NC) load(s, s);

    for (int c = 0; c < NC; c++) {
        int ahead = NC - 1 - c;
        if (ahead >= 2)      asm volatile("cp.async.wait_group 2;" ::: "memory");
        else if (ahead == 1) asm volatile("cp.async.wait_group 1;" ::: "memory");
        else                 asm volatile("cp.async.wait_group 0;" ::: "memory");
        __syncthreads();
        if (c + N_STAGE - 1 < NC) load(c + N_STAGE - 1, (c + N_STAGE - 1) & 3);

        const uint32_t au = a_frag + (c & 3) * STAGE_BYTES;
        const uint32_t bu = b_frag + (c & 3) * STAGE_BYTES;
        #pragma unroll
        for (int ks = 0; ks < 2; ks++) {
            uint32_t af[4][4], bf[2][4];
            #pragma unroll
            for (int i = 0; i < 4; i++)
                ldm_x4(af[i], au + i * (16 * A_STRIDE * 2) + ks * 32);
            ldm_x4_t(bf[0], bu + ks * (16 * B_STRIDE * 2));
            ldm_x4_t(bf[1], bu + ks * (16 * B_STRIDE * 2) + 32);
            #pragma unroll
            for (int i = 0; i < 4; i++)
                #pragma unroll
                for (int j = 0; j < 4; j++)
                    mma16(acc[i][j], af[i], &bf[j >> 1][(j & 1) * 2]);
        }
    }

    #pragma unroll
    for (int i = 0; i < 4; i++) {
        const int r0 = mb + wm * 64 + i * 16 + g;
        #pragma unroll
        for (int j = 0; j < 4; j++) {
            const int col = nb + wn * 32 + j * 8 + 2 * tq;
            float v0 = acc[i][j][0], v1 = acc[i][j][1];
            float v2 = acc[i][j][2], v3 = acc[i][j][3];
            {
                float2 bb = *reinterpret_cast<const float2*>(bias + col);
                v0 += bb.x; v1 += bb.y; v2 += bb.x; v3 += bb.y;
            }
            if (EPI == 2) {
                v0 = 0.5f * v0 * (1.0f + erff(v0 * 0.70710678118654752f));
                v1 = 0.5f * v1 * (1.0f + erff(v1 * 0.70710678118654752f));
                v2 = 0.5f * v2 * (1.0f + erff(v2 * 0.70710678118654752f));
                v3 = 0.5f * v3 * (1.0f + erff(v3 * 0.70710678118654752f));
            }
            if (EPI == 3) {
                float2 r1 = *reinterpret_cast<const float2*>(Rb + (size_t)r0 * N + col);
                float2 r2 = *reinterpret_cast<const float2*>(Rb + (size_t)(r0 + 8) * N + col);
                v0 += r1.x; v1 += r1.y; v2 += r2.x; v3 += r2.y;
            }
            store2(Cb + (size_t)r0 * N + col,       v0, v1);
            store2(Cb + (size_t)(r0 + 8) * N + col, v2, v3);
        }
    }
}

// ---------------------------------------------------------------------------
// Launch graph
// ---------------------------------------------------------------------------
extern "C" void kernel_launch(void* const* d_in, const int* in_sizes, int n_in,
                              void* d_out, int out_size)
{
    (void)in_sizes; (void)n_in; (void)out_size;
    const float* x    = (const float*)d_in[0];
    const float* ln1g = (const float*)d_in[1];
    const float* ln1b = (const float*)d_in[2];
    const float* Wq   = (const float*)d_in[3];
    const float* bq   = (const float*)d_in[4];
    const float* Wk   = (const float*)d_in[5];
    const float* bk   = (const float*)d_in[6];
    const float* Wv   = (const float*)d_in[7];
    const float* bv   = (const float*)d_in[8];
    const float* Wo   = (const float*)d_in[9];
    const float* bo   = (const float*)d_in[10];
    const float* ln2g = (const float*)d_in[11];
    const float* ln2b = (const float*)d_in[12];
    const float* W1   = (const float*)d_in[13];
    const float* b1   = (const float*)d_in[14];
    const float* W2   = (const float*)d_in[15];
    const float* b2   = (const float*)d_in[16];
    float* out = (float*)d_out;

    float *xn, *y, *bqkv;
    __half *xnh, *qkvh, *hoh, *hh, *midh;
    __half *wqkvh, *woh, *w1h, *w2h;
    cudaGetSymbolAddress((void**)&xn,    g_xn);
    cudaGetSymbolAddress((void**)&xnh,   g_xnh);
    cudaGetSymbolAddress((void**)&qkvh,  g_qkvh);
    cudaGetSymbolAddress((void**)&hoh,   g_hoh);
    cudaGetSymbolAddress((void**)&y,     g_y);
    cudaGetSymbolAddress((void**)&hh,    g_hh);
    cudaGetSymbolAddress((void**)&midh,  g_midh);
    cudaGetSymbolAddress((void**)&wqkvh, g_wqkvh);
    cudaGetSymbolAddress((void**)&bqkv,  g_bqkv);
    cudaGetSymbolAddress((void**)&woh,   g_woh);
    cudaGetSymbolAddress((void**)&w1h,   g_w1h);
    cudaGetSymbolAddress((void**)&w2h,   g_w2h);

    cudaFuncSetAttribute(gemm_h<1, __half>, cudaFuncAttributeMaxDynamicSharedMemorySize, SM_TOT);
    cudaFuncSetAttribute(gemm_h<2, __half>, cudaFuncAttributeMaxDynamicSharedMemorySize, SM_TOT);
    cudaFuncSetAttribute(gemm_h<3, float>,  cudaFuncAttributeMaxDynamicSharedMemorySize, SM_TOT);
    cudaFuncSetAttribute(flash_kernel, cudaFuncAttributeMaxDynamicSharedMemorySize, FA_SMEM);

    const float scale2 = 0.08838834764831845f * 1.4426950408889634f; // /sqrt(128)*log2e

    // 0. single prep launch: pack/convert all weights
    prep_kernel<<<(PK_TOT + 255) / 256, 256>>>(Wq, Wk, Wv, bq, bk, bv, Wo, W1, W2,
                                               wqkvh, bqkv, woh, w1h, w2h);

    // 1. xn = LN1(x)  (fp32 + fp16)
    ln_kernel<true, true><<<R_, 256>>>(x, ln1g, ln1b, xn, xnh);

    // 2. qkv = xnh @ Wqkv + bqkv  -> fp16 [R,384]
    gemm_h<1, __half><<<dim3(3, 128, 1), 256, SM_TOT>>>(xnh, wqkvh, bqkv, nullptr, qkvh, R_, 384, D_);

    // 3. flash attention -> fp16 ho
    flash_kernel<<<dim3(S_ / 128, B_), 256, FA_SMEM>>>(qkvh, hoh, scale2);

    // 4. y = xn + ho @ Wo + bo  -> fp32
    gemm_h<3, float><<<dim3(8, 128, 1), 256, SM_TOT>>>(hoh, woh, bo, xn, y, R_, D_, DK_);

    // 5. h = LN2(y) -> fp16
    ln_kernel<false, true><<<R_, 256>>>(y, ln2g, ln2b, nullptr, hh);

    // 6. mid = gelu(h @ W1 + b1)  -> fp16
    gemm_h<2, __half><<<dim3(32, 128, 1), 256, SM_TOT>>>(hh, w1h, b1, nullptr, midh, R_, H_, D_);

    // 7. out = y + mid @ W2 + b2  -> fp32
    gemm_h<3, float><<<dim3(8, 128, 1), 256, SM_TOT>>>(midh, w2h, b2, y, out, R_, D_, H_);
}